// round 10
// baseline (speedup 1.0000x reference)
#include <cuda_runtime.h>
#include <cuda_bf16.h>
#include <cstdint>

#define NN 50000
#define HID 128
#define PCOLS 384
#define SENT ((int)0x80000000)

// ---------------- scratch (device globals; no runtime allocation) ----------
__device__ float g_P[NN * PCOLS];                            // [A | B | U1] fp32
__device__ int   g_M[NN * HID];                              // encoded segment-max
__device__ __align__(16) __nv_bfloat16 g_Bh[4 * 128 * 128];  // W blocks, [n][k], hi
__device__ __align__(16) __nv_bfloat16 g_Bl[4 * 128 * 128];  // W blocks, [n][k], lo
__device__ __align__(16) __nv_bfloat16 g_Zh[NN * HID];       // z split hi
__device__ __align__(16) __nv_bfloat16 g_Zl[NN * HID];       // z split lo

// ---------------- float<->int order-preserving encode ----------------------
__device__ __forceinline__ int encf(float f) {
    int i = __float_as_int(f);
    return i >= 0 ? i : i ^ 0x7fffffff;
}
__device__ __forceinline__ float decf(int i) {
    return __int_as_float(i >= 0 ? i : i ^ 0x7fffffff);
}

// ---------------- mma/ldmatrix helpers (portable: sm_80+, no 'a' features) -
__device__ __forceinline__ uint32_t smem_u32(const void* p) {
    uint32_t a;
    asm("{ .reg .u64 t; cvta.to.shared.u64 t, %1; cvt.u32.u64 %0, t; }"
        : "=r"(a) : "l"(p));
    return a;
}
__device__ __forceinline__ void ldsm_x4(uint32_t* r, uint32_t addr) {
    asm volatile("ldmatrix.sync.aligned.m8n8.x4.shared.b16 {%0,%1,%2,%3},[%4];"
                 : "=r"(r[0]), "=r"(r[1]), "=r"(r[2]), "=r"(r[3]) : "r"(addr));
}
__device__ __forceinline__ void ldsm_x2(uint32_t* r, uint32_t addr) {
    asm volatile("ldmatrix.sync.aligned.m8n8.x2.shared.b16 {%0,%1},[%2];"
                 : "=r"(r[0]), "=r"(r[1]) : "r"(addr));
}
__device__ __forceinline__ void mma_bf16(float* c, const uint32_t* a,
                                         const uint32_t* b) {
    asm volatile(
        "mma.sync.aligned.m16n8k16.row.col.f32.bf16.bf16.f32 "
        "{%0,%1,%2,%3}, {%4,%5,%6,%7}, {%8,%9}, {%0,%1,%2,%3};"
        : "+f"(c[0]), "+f"(c[1]), "+f"(c[2]), "+f"(c[3])
        : "r"(a[0]), "r"(a[1]), "r"(a[2]), "r"(a[3]), "r"(b[0]), "r"(b[1]));
}

// split 8 fp32 -> 8 bf16 hi + 8 bf16 lo packed as uint4
__device__ __forceinline__ void split8(const float* v, uint4& h4, uint4& l4) {
    unsigned hs[8], ls[8];
#pragma unroll
    for (int i = 0; i < 8; ++i) {
        float a = v[i];
        __nv_bfloat16 hb = __float2bfloat16_rn(a);
        float r = a - __bfloat162float(hb);
        __nv_bfloat16 lb = __float2bfloat16_rn(r);
        hs[i] = (unsigned)*(unsigned short*)&hb;
        ls[i] = (unsigned)*(unsigned short*)&lb;
    }
    h4 = make_uint4(hs[0] | (hs[1] << 16), hs[2] | (hs[3] << 16),
                    hs[4] | (hs[5] << 16), hs[6] | (hs[7] << 16));
    l4 = make_uint4(ls[0] | (ls[1] << 16), ls[2] | (ls[3] << 16),
                    ls[4] | (ls[5] << 16), ls[6] | (ls[7] << 16));
}

// SMEM tile geometry: [128 rows][128 k] bf16, padded stride (conflict-free ldmatrix)
#define SA 136
#define TILE_B (128 * SA * 2)   // 34816 bytes
#define SM_AH 0
#define SM_AL (TILE_B)
#define SM_BH (2 * TILE_B)
#define SM_BL (3 * TILE_B)
#define DYN_BYTES (4 * TILE_B)

// ---------------------------------------------------------------------------
// init sentinel
// ---------------------------------------------------------------------------
__global__ void k_init(int n4) {
    int i = blockIdx.x * blockDim.x + threadIdx.x;
    if (i < n4) ((int4*)g_M)[i] = make_int4(SENT, SENT, SENT, SENT);
}

// ---------------------------------------------------------------------------
// prep weights: transpose+split into bf16 [n][k] blocks
//   blk0=Wm[0:128], blk1=Wm[128:256], blk2=Wu[0:128], blk3=Wu[128:256]
// ---------------------------------------------------------------------------
__global__ void k_prepw(const float* __restrict__ Wm, const float* __restrict__ Wu) {
    int idx = blockIdx.x * blockDim.x + threadIdx.x;
    if (idx >= 4 * 128 * 128) return;
    int blk = idx >> 14, n = (idx >> 7) & 127, k = idx & 127;
    float v;
    if (blk == 0)      v = Wm[k * HID + n];
    else if (blk == 1) v = Wm[(128 + k) * HID + n];
    else if (blk == 2) v = Wu[k * HID + n];
    else               v = Wu[(128 + k) * HID + n];
    __nv_bfloat16 hb = __float2bfloat16_rn(v);
    float r = v - __bfloat162float(hb);
    g_Bh[idx] = hb;
    g_Bl[idx] = __float2bfloat16_rn(r);
}

// ---------------------------------------------------------------------------
// prep z: split fp32 -> bf16 hi/lo (8 elems / thread)
// ---------------------------------------------------------------------------
__global__ void k_prepz(const float* __restrict__ z, int n8) {
    int i = blockIdx.x * blockDim.x + threadIdx.x;
    if (i >= n8) return;
    float v[8];
    *(float4*)&v[0] = *(const float4*)&z[i * 8];
    *(float4*)&v[4] = *(const float4*)&z[i * 8 + 4];
    uint4 h4, l4;
    split8(v, h4, l4);
    ((uint4*)g_Zh)[i] = h4;
    ((uint4*)g_Zl)[i] = l4;
}

// ---------------------------------------------------------------------------
// warp-level 64x32 mma core over the 4 smem tiles (3-pass error split)
//   acc[mt][nt][4] += sum over K=128
// ---------------------------------------------------------------------------
__device__ __forceinline__ void warp_mma_3pass(const char* sm, float acc[4][4][4],
                                               int wm, int wn, int lane) {
    const int pa[3] = {SM_AH, SM_AH, SM_AL};
    const int pb[3] = {SM_BH, SM_BL, SM_BH};
    uint32_t a_row = wm * 64 + (lane & 15);
    uint32_t a_colb = (lane >> 4) * 16;            // byte offset of 8-col block
    uint32_t b_row = wn * 32 + (lane & 7);
    uint32_t b_colb = ((lane >> 3) & 1) * 16;
#pragma unroll
    for (int p = 0; p < 3; ++p) {
        uint32_t abase = smem_u32(sm + pa[p]);
        uint32_t bbase = smem_u32(sm + pb[p]);
#pragma unroll
        for (int kk = 0; kk < 8; ++kk) {
            uint32_t k0b = kk * 32;                // 16 bf16 = 32 bytes
            uint32_t a[4][4], b[4][2];
#pragma unroll
            for (int mt = 0; mt < 4; ++mt)
                ldsm_x4(a[mt], abase + (a_row + mt * 16) * (SA * 2) + k0b + a_colb);
#pragma unroll
            for (int nt = 0; nt < 4; ++nt)
                ldsm_x2(b[nt], bbase + (b_row + nt * 8) * (SA * 2) + k0b + b_colb);
#pragma unroll
            for (int mt = 0; mt < 4; ++mt)
#pragma unroll
                for (int nt = 0; nt < 4; ++nt)
                    mma_bf16(acc[mt][nt], a[mt], b[nt]);
        }
    }
}

__device__ __forceinline__ void load_B_tile(char* sm, int blk, int tid) {
    int n = tid >> 1, kh = (tid & 1) * 64;
    const uint4* bh = (const uint4*)&g_Bh[(blk * 128 + n) * 128 + kh];
    const uint4* bl = (const uint4*)&g_Bl[(blk * 128 + n) * 128 + kh];
    char* dh = sm + SM_BH + n * (SA * 2) + kh * 2;
    char* dl = sm + SM_BL + n * (SA * 2) + kh * 2;
#pragma unroll
    for (int c = 0; c < 8; ++c) {
        *(uint4*)(dh + c * 16) = bh[c];
        *(uint4*)(dl + c * 16) = bl[c];
    }
}

// ---------------------------------------------------------------------------
// GEMM 1: P[:, cb*128:+128] = z @ Wblk(cb);  grid (nblk, 3)
// ---------------------------------------------------------------------------
__global__ void __launch_bounds__(256, 1)
k_mgemm1() {
    extern __shared__ __align__(16) char sm[];
    int tid = threadIdx.x, wid = tid >> 5, lane = tid & 31;
    int wm = wid >> 2, wn = wid & 3;
    int rowbase = blockIdx.x * 128, cb = blockIdx.y;

    // fill A (copy pre-split z) and B
    {
        int r = tid >> 1, kh = (tid & 1) * 64;
        int row = rowbase + r;
        char* dh = sm + SM_AH + r * (SA * 2) + kh * 2;
        char* dl = sm + SM_AL + r * (SA * 2) + kh * 2;
        if (row < NN) {
            const uint4* zh = (const uint4*)&g_Zh[row * HID + kh];
            const uint4* zl = (const uint4*)&g_Zl[row * HID + kh];
#pragma unroll
            for (int c = 0; c < 8; ++c) {
                *(uint4*)(dh + c * 16) = zh[c];
                *(uint4*)(dl + c * 16) = zl[c];
            }
        } else {
            uint4 zz = make_uint4(0, 0, 0, 0);
#pragma unroll
            for (int c = 0; c < 8; ++c) {
                *(uint4*)(dh + c * 16) = zz;
                *(uint4*)(dl + c * 16) = zz;
            }
        }
    }
    load_B_tile(sm, cb, tid);
    __syncthreads();

    float acc[4][4][4];
#pragma unroll
    for (int i = 0; i < 4; ++i)
#pragma unroll
        for (int j = 0; j < 4; ++j)
#pragma unroll
            for (int q = 0; q < 4; ++q) acc[i][j][q] = 0.f;

    warp_mma_3pass(sm, acc, wm, wn, lane);

    // epilogue: scatter accumulators to g_P
    int gid = lane >> 2, tig = lane & 3;
#pragma unroll
    for (int mt = 0; mt < 4; ++mt) {
        int r0 = rowbase + wm * 64 + mt * 16 + gid;
#pragma unroll
        for (int nt = 0; nt < 4; ++nt) {
            int col = cb * 128 + wn * 32 + nt * 8 + tig * 2;
            if (r0 < NN)
                *(float2*)&g_P[r0 * PCOLS + col] =
                    make_float2(acc[mt][nt][0], acc[mt][nt][1]);
            if (r0 + 8 < NN)
                *(float2*)&g_P[(r0 + 8) * PCOLS + col] =
                    make_float2(acc[mt][nt][2], acc[mt][nt][3]);
        }
    }
}

// ---------------------------------------------------------------------------
// Edge phase: one warp per edge.  atomicMax(M[dst], enc(B[src] + w*r))
// ---------------------------------------------------------------------------
__global__ void k_edge(const int* __restrict__ src, const int* __restrict__ dst,
                       const float* __restrict__ w, const float* __restrict__ Wm,
                       int E) {
    int gw = (blockIdx.x * blockDim.x + threadIdx.x) >> 5;
    int lane = threadIdx.x & 31;
    if (gw >= E) return;
    int   s  = __ldg(&src[gw]);
    int   d  = __ldg(&dst[gw]);
    float we = __ldg(&w[gw]);
    float4 r4 = *(const float4*)&Wm[256 * HID + lane * 4];
    float4 b  = *(const float4*)&g_P[s * PCOLS + 128 + lane * 4];
    int* mp = &g_M[d * HID + lane * 4];
    atomicMax(mp + 0, encf(fmaf(we, r4.x, b.x)));
    atomicMax(mp + 1, encf(fmaf(we, r4.y, b.y)));
    atomicMax(mp + 2, encf(fmaf(we, r4.z, b.z)));
    atomicMax(mp + 3, encf(fmaf(we, r4.w, b.w)));
}

// ---------------------------------------------------------------------------
// GEMM 2: h = m @ Wu2 + U1 + bu; m[n,k] = (M==SENT) ? 0 : A + bm + dec(M)
// ---------------------------------------------------------------------------
__global__ void __launch_bounds__(256, 1)
k_mgemm2(const float* __restrict__ bm, const float* __restrict__ bu,
         float* __restrict__ h) {
    extern __shared__ __align__(16) char sm[];
    int tid = threadIdx.x, wid = tid >> 5, lane = tid & 31;
    int wm = wid >> 2, wn = wid & 3;
    int rowbase = blockIdx.x * 128;

    // build m rows -> split -> smem A
    {
        int r = tid >> 1, kh = (tid & 1) * 64;
        int row = rowbase + r;
        char* dh = sm + SM_AH + r * (SA * 2) + kh * 2;
        char* dl = sm + SM_AL + r * (SA * 2) + kh * 2;
        float v[8];
#pragma unroll
        for (int c = 0; c < 64; c += 8) {
            if (row < NN) {
                int kg = kh + c;
                float4 a0 = *(const float4*)&g_P[row * PCOLS + kg];
                float4 a1 = *(const float4*)&g_P[row * PCOLS + kg + 4];
                int4   m0 = *(const int4*)&g_M[row * HID + kg];
                int4   m1 = *(const int4*)&g_M[row * HID + kg + 4];
                float4 b0 = *(const float4*)&bm[kg];
                float4 b1 = *(const float4*)&bm[kg + 4];
                v[0] = (m0.x == SENT) ? 0.f : a0.x + b0.x + decf(m0.x);
                v[1] = (m0.y == SENT) ? 0.f : a0.y + b0.y + decf(m0.y);
                v[2] = (m0.z == SENT) ? 0.f : a0.z + b0.z + decf(m0.z);
                v[3] = (m0.w == SENT) ? 0.f : a0.w + b0.w + decf(m0.w);
                v[4] = (m1.x == SENT) ? 0.f : a1.x + b1.x + decf(m1.x);
                v[5] = (m1.y == SENT) ? 0.f : a1.y + b1.y + decf(m1.y);
                v[6] = (m1.z == SENT) ? 0.f : a1.z + b1.z + decf(m1.z);
                v[7] = (m1.w == SENT) ? 0.f : a1.w + b1.w + decf(m1.w);
            } else {
#pragma unroll
                for (int i = 0; i < 8; ++i) v[i] = 0.f;
            }
            uint4 h4, l4;
            split8(v, h4, l4);
            *(uint4*)(dh + c * 2) = h4;
            *(uint4*)(dl + c * 2) = l4;
        }
    }
    load_B_tile(sm, 3, tid);   // Wu2
    __syncthreads();

    float acc[4][4][4];
#pragma unroll
    for (int i = 0; i < 4; ++i)
#pragma unroll
        for (int j = 0; j < 4; ++j)
#pragma unroll
            for (int q = 0; q < 4; ++q) acc[i][j][q] = 0.f;

    warp_mma_3pass(sm, acc, wm, wn, lane);

    // epilogue: h = acc + U1 + bu
    int gid = lane >> 2, tig = lane & 3;
#pragma unroll
    for (int mt = 0; mt < 4; ++mt) {
        int r0 = rowbase + wm * 64 + mt * 16 + gid;
#pragma unroll
        for (int nt = 0; nt < 4; ++nt) {
            int col = wn * 32 + nt * 8 + tig * 2;
            float2 bb = *(const float2*)&bu[col];
            if (r0 < NN) {
                float2 uu = *(const float2*)&g_P[r0 * PCOLS + 256 + col];
                *(float2*)&h[r0 * HID + col] =
                    make_float2(acc[mt][nt][0] + uu.x + bb.x,
                                acc[mt][nt][1] + uu.y + bb.y);
            }
            if (r0 + 8 < NN) {
                float2 uu = *(const float2*)&g_P[(r0 + 8) * PCOLS + 256 + col];
                *(float2*)&h[(r0 + 8) * HID + col] =
                    make_float2(acc[mt][nt][2] + uu.x + bb.x,
                                acc[mt][nt][3] + uu.y + bb.y);
            }
        }
    }
}

// ---------------------------------------------------------------------------
extern "C" void kernel_launch(void* const* d_in, const int* in_sizes, int n_in,
                              void* d_out, int out_size) {
    const float* z   = (const float*)d_in[0];
    const float* w   = (const float*)d_in[1];
    const int*   src = (const int*)d_in[2];
    const int*   dst = (const int*)d_in[3];
    const float* Wm  = (const float*)d_in[4];
    const float* bm  = (const float*)d_in[5];
    const float* Wu  = (const float*)d_in[6];
    const float* bu  = (const float*)d_in[7];
    float* h = (float*)d_out;
    int E = in_sizes[2];

    static bool attr_done = false;
    if (!attr_done) {
        cudaFuncSetAttribute(k_mgemm1, cudaFuncAttributeMaxDynamicSharedMemorySize,
                             DYN_BYTES);
        cudaFuncSetAttribute(k_mgemm2, cudaFuncAttributeMaxDynamicSharedMemorySize,
                             DYN_BYTES);
        attr_done = true;
    }

    int n4 = NN * HID / 4;
    k_init<<<(n4 + 255) / 256, 256>>>(n4);
    k_prepw<<<(4 * 128 * 128 + 255) / 256, 256>>>(Wm, Wu);
    int n8 = NN * HID / 8;
    k_prepz<<<(n8 + 255) / 256, 256>>>(z, n8);

    int nblk = (NN + 127) / 128;
    dim3 g1(nblk, 3);
    k_mgemm1<<<g1, 256, DYN_BYTES>>>();

    int eblocks = (E * 32 + 255) / 256;
    k_edge<<<eblocks, 256>>>(src, dst, w, Wm, E);

    k_mgemm2<<<nblk, 256, DYN_BYTES>>>(bm, bu, h);
}

// round 12
// speedup vs baseline: 1.8428x; 1.8428x over previous
#include <cuda_runtime.h>
#include <cuda_bf16.h>
#include <cstdint>

#define NN 50000
#define HID 128
#define PCOLS 384
#define EMAX 1048576
#define NINF __int_as_float(0xff800000)

// ---------------- scratch (device globals; no runtime allocation) ----------
__device__ float g_P[NN * PCOLS];                            // [A | B | U1] fp32
__device__ float g_Mf[NN * HID];                             // per-node max (fp32)
__device__ __align__(16) __nv_bfloat16 g_Bh[4 * 128 * 128];  // W blocks [n][k] hi
__device__ __align__(16) __nv_bfloat16 g_Bl[4 * 128 * 128];  // W blocks [n][k] lo
__device__ int    g_cnt[NN];       // node degree
__device__ int    g_off[NN];       // CSR offsets
__device__ int    g_cur[NN];       // scatter cursors
__device__ int    g_blk[256];      // scan partials
__device__ float2 g_es[EMAX];      // packed (src bits, w) grouped by dst

// ---------------- mma/ldmatrix helpers (portable, no 'a' features) ----------
__device__ __forceinline__ uint32_t smem_u32(const void* p) {
    uint32_t a;
    asm("{ .reg .u64 t; cvta.to.shared.u64 t, %1; cvt.u32.u64 %0, t; }"
        : "=r"(a) : "l"(p));
    return a;
}
__device__ __forceinline__ void ldsm_x4(uint32_t* r, uint32_t addr) {
    asm volatile("ldmatrix.sync.aligned.m8n8.x4.shared.b16 {%0,%1,%2,%3},[%4];"
                 : "=r"(r[0]), "=r"(r[1]), "=r"(r[2]), "=r"(r[3]) : "r"(addr));
}
__device__ __forceinline__ void mma_bf16(float* c, const uint32_t* a,
                                         const uint32_t* b) {
    asm volatile(
        "mma.sync.aligned.m16n8k16.row.col.f32.bf16.bf16.f32 "
        "{%0,%1,%2,%3}, {%4,%5,%6,%7}, {%8,%9}, {%0,%1,%2,%3};"
        : "+f"(c[0]), "+f"(c[1]), "+f"(c[2]), "+f"(c[3])
        : "r"(a[0]), "r"(a[1]), "r"(a[2]), "r"(a[3]), "r"(b[0]), "r"(b[1]));
}

// split 8 fp32 -> bf16 hi/lo packed as uint4
__device__ __forceinline__ void split8(const float* v, uint4& h4, uint4& l4) {
    unsigned hs[8], ls[8];
#pragma unroll
    for (int i = 0; i < 8; ++i) {
        float a = v[i];
        __nv_bfloat16 hb = __float2bfloat16_rn(a);
        float r = a - __bfloat162float(hb);
        __nv_bfloat16 lb = __float2bfloat16_rn(r);
        hs[i] = (unsigned)*(unsigned short*)&hb;
        ls[i] = (unsigned)*(unsigned short*)&lb;
    }
    h4 = make_uint4(hs[0] | (hs[1] << 16), hs[2] | (hs[3] << 16),
                    hs[4] | (hs[5] << 16), hs[6] | (hs[7] << 16));
    l4 = make_uint4(ls[0] | (ls[1] << 16), ls[2] | (ls[3] << 16),
                    ls[4] | (ls[5] << 16), ls[6] | (ls[7] << 16));
}

// SMEM tile: [128 rows][128 k] bf16, padded stride 136 (conflict-free ldmatrix)
#define SA 136
#define SROW (SA * 2)            // 272 bytes/row
#define TILE_B (128 * SROW)      // 34816
#define SM_AH 0
#define SM_AL (TILE_B)
#define SM_BH (2 * TILE_B)
#define SM_BL (3 * TILE_B)
#define DYN_BYTES (4 * TILE_B)

// ---------------------------------------------------------------------------
// prep weights: transpose+split into bf16 [n][k] blocks
// ---------------------------------------------------------------------------
__global__ void k_prepw(const float* __restrict__ Wm, const float* __restrict__ Wu) {
    int idx = blockIdx.x * blockDim.x + threadIdx.x;
    if (idx >= 4 * 128 * 128) return;
    int blk = idx >> 14, n = (idx >> 7) & 127, k = idx & 127;
    float v;
    if (blk == 0)      v = Wm[k * HID + n];
    else if (blk == 1) v = Wm[(128 + k) * HID + n];
    else if (blk == 2) v = Wu[k * HID + n];
    else               v = Wu[(128 + k) * HID + n];
    __nv_bfloat16 hb = __float2bfloat16_rn(v);
    float r = v - __bfloat162float(hb);
    g_Bh[idx] = hb;
    g_Bl[idx] = __float2bfloat16_rn(r);
}

// ---------------------------------------------------------------------------
// counting sort of edges by destination
// ---------------------------------------------------------------------------
__global__ void k_zero() {
    int i = blockIdx.x * blockDim.x + threadIdx.x;
    if (i < NN) { g_cnt[i] = 0; g_cur[i] = 0; }
}
__global__ void k_hist(const int* __restrict__ dst, int E) {
    int e = blockIdx.x * blockDim.x + threadIdx.x;
    if (e < E) atomicAdd(&g_cnt[dst[e]], 1);
}
__global__ void k_scan1() {   // per-256-chunk sums
    __shared__ int s[256];
    int t = threadIdx.x, i = blockIdx.x * 256 + t;
    s[t] = (i < NN) ? g_cnt[i] : 0;
    __syncthreads();
    for (int o = 128; o > 0; o >>= 1) {
        if (t < o) s[t] += s[t + o];
        __syncthreads();
    }
    if (t == 0) g_blk[blockIdx.x] = s[0];
}
__global__ void k_scan2(int nblk) {  // exclusive scan of partials (1 block)
    __shared__ int s[256];
    int t = threadIdx.x;
    int v = (t < nblk) ? g_blk[t] : 0;
    s[t] = v;
    __syncthreads();
    for (int o = 1; o < 256; o <<= 1) {
        int x = (t >= o) ? s[t - o] : 0;
        __syncthreads();
        s[t] += x;
        __syncthreads();
    }
    if (t < nblk) g_blk[t] = s[t] - v;
}
__global__ void k_scan3() {   // per-chunk exclusive scan + base
    __shared__ int s[256];
    int t = threadIdx.x, i = blockIdx.x * 256 + t;
    int v = (i < NN) ? g_cnt[i] : 0;
    s[t] = v;
    __syncthreads();
    for (int o = 1; o < 256; o <<= 1) {
        int x = (t >= o) ? s[t - o] : 0;
        __syncthreads();
        s[t] += x;
        __syncthreads();
    }
    if (i < NN) g_off[i] = s[t] - v + g_blk[blockIdx.x];
}
__global__ void k_scatter(const int* __restrict__ src, const int* __restrict__ dst,
                          const float* __restrict__ w, int E) {
    int e = blockIdx.x * blockDim.x + threadIdx.x;
    if (e >= E) return;
    int d = dst[e];
    int p = g_off[d] + atomicAdd(&g_cur[d], 1);
    if (p < EMAX) g_es[p] = make_float2(__int_as_float(src[e]), w[e]);
}

// ---------------------------------------------------------------------------
// node max: one warp per node, no atomics
//   mx[n] = max over edges (B[src] + w * r)
// ---------------------------------------------------------------------------
__global__ void __launch_bounds__(256)
k_nodemax(const float* __restrict__ Wm) {
    int n = (blockIdx.x * blockDim.x + threadIdx.x) >> 5;
    int lane = threadIdx.x & 31;
    if (n >= NN) return;
    int deg = g_cnt[n];
    if (deg == 0) return;
    float4 r4 = *(const float4*)&Wm[256 * HID + lane * 4];
    float4 mx = make_float4(NINF, NINF, NINF, NINF);
    int base = g_off[n];
    for (int c = 0; c < deg; c += 32) {
        int mcnt = min(32, deg - c);
        float2 sw = make_float2(0.f, 0.f);
        if (lane < mcnt) sw = g_es[base + c + lane];
#pragma unroll 4
        for (int j = 0; j < mcnt; ++j) {
            int   s  = __shfl_sync(0xffffffffu, __float_as_int(sw.x), j);
            float we = __shfl_sync(0xffffffffu, sw.y, j);
            float4 b = *(const float4*)&g_P[s * PCOLS + 128 + lane * 4];
            mx.x = fmaxf(mx.x, fmaf(we, r4.x, b.x));
            mx.y = fmaxf(mx.y, fmaf(we, r4.y, b.y));
            mx.z = fmaxf(mx.z, fmaf(we, r4.z, b.z));
            mx.w = fmaxf(mx.w, fmaf(we, r4.w, b.w));
        }
    }
    *(float4*)&g_Mf[n * HID + lane * 4] = mx;
}

// ---------------------------------------------------------------------------
// warp-level 32x32 mma core (3-pass error split); 16 warps in 4x4 grid
// ---------------------------------------------------------------------------
__device__ __forceinline__ void warp_mma_3pass(const char* sm, float acc[2][4][4],
                                               int wm, int wn, int lane) {
    const int pa[3] = {SM_AH, SM_AH, SM_AL};
    const int pb[3] = {SM_BH, SM_BL, SM_BH};
    // A: m16 frags via ldsm_x4 — rows wm*32 + mt*16 + (lane&15), col half by lane>>4
    uint32_t a_row  = wm * 32 + (lane & 15);
    uint32_t a_colb = (lane >> 4) * 16;
    // B: pairs of n8 frags via ldsm_x4 — group g=lane>>3: (nt pair, k-phase)
    int g = lane >> 3;
    uint32_t b_rowi = (g >> 1) * 8 + (lane & 7);   // within pair
    uint32_t b_colb = (g & 1) * 16;
#pragma unroll
    for (int p = 0; p < 3; ++p) {
        uint32_t abase = smem_u32(sm + pa[p]);
        uint32_t bbase = smem_u32(sm + pb[p]);
#pragma unroll
        for (int kk = 0; kk < 8; ++kk) {
            uint32_t k0b = kk * 32;
            uint32_t a[2][4], b[4][2];
#pragma unroll
            for (int mt = 0; mt < 2; ++mt)
                ldsm_x4(a[mt], abase + (a_row + mt * 16) * SROW + k0b + a_colb);
#pragma unroll
            for (int pp = 0; pp < 2; ++pp) {
                uint32_t r[4];
                ldsm_x4(r, bbase + (wn * 32 + pp * 16 + b_rowi) * SROW + k0b + b_colb);
                b[pp * 2 + 0][0] = r[0]; b[pp * 2 + 0][1] = r[1];
                b[pp * 2 + 1][0] = r[2]; b[pp * 2 + 1][1] = r[3];
            }
#pragma unroll
            for (int mt = 0; mt < 2; ++mt)
#pragma unroll
                for (int nt = 0; nt < 4; ++nt)
                    mma_bf16(acc[mt][nt], a[mt], b[nt]);
        }
    }
}

__device__ __forceinline__ void load_B_tile(char* sm, int blk, int tid) {
    int n = tid >> 2, kq = (tid & 3) * 32;        // 32 bf16 per thread
    const uint4* bh = (const uint4*)&g_Bh[(blk * 128 + n) * 128 + kq];
    const uint4* bl = (const uint4*)&g_Bl[(blk * 128 + n) * 128 + kq];
    char* dh = sm + SM_BH + n * SROW + kq * 2;
    char* dl = sm + SM_BL + n * SROW + kq * 2;
#pragma unroll
    for (int c = 0; c < 4; ++c) {
        *(uint4*)(dh + c * 16) = bh[c];
        *(uint4*)(dl + c * 16) = bl[c];
    }
}

// ---------------------------------------------------------------------------
// GEMM 1: P[:, cb*128:+128] = z @ Wblk(cb);  grid (nblk, 3), 512 threads
// ---------------------------------------------------------------------------
__global__ void __launch_bounds__(512, 1)
k_mgemm1(const float* __restrict__ z) {
    extern __shared__ __align__(16) char sm[];
    int tid = threadIdx.x, wid = tid >> 5, lane = tid & 31;
    int wm = wid >> 2, wn = wid & 3;
    int rowbase = blockIdx.x * 128, cb = blockIdx.y;

    // fill A: split z rows in-kernel (32 fp32 per thread)
    {
        int r = tid >> 2, kq = (tid & 3) * 32;
        int row = rowbase + r;
        char* dh = sm + SM_AH + r * SROW + kq * 2;
        char* dl = sm + SM_AL + r * SROW + kq * 2;
        float v[8];
#pragma unroll
        for (int c = 0; c < 32; c += 8) {
            if (row < NN) {
                *(float4*)&v[0] = *(const float4*)&z[row * HID + kq + c];
                *(float4*)&v[4] = *(const float4*)&z[row * HID + kq + c + 4];
            } else {
#pragma unroll
                for (int i = 0; i < 8; ++i) v[i] = 0.f;
            }
            uint4 h4, l4;
            split8(v, h4, l4);
            *(uint4*)(dh + c * 2) = h4;
            *(uint4*)(dl + c * 2) = l4;
        }
    }
    load_B_tile(sm, cb, tid);
    __syncthreads();

    float acc[2][4][4];
#pragma unroll
    for (int i = 0; i < 2; ++i)
#pragma unroll
        for (int j = 0; j < 4; ++j)
#pragma unroll
            for (int q = 0; q < 4; ++q) acc[i][j][q] = 0.f;

    warp_mma_3pass(sm, acc, wm, wn, lane);

    int gid = lane >> 2, tig = lane & 3;
#pragma unroll
    for (int mt = 0; mt < 2; ++mt) {
        int r0 = rowbase + wm * 32 + mt * 16 + gid;
#pragma unroll
        for (int nt = 0; nt < 4; ++nt) {
            int col = cb * 128 + wn * 32 + nt * 8 + tig * 2;
            if (r0 < NN)
                *(float2*)&g_P[r0 * PCOLS + col] =
                    make_float2(acc[mt][nt][0], acc[mt][nt][1]);
            if (r0 + 8 < NN)
                *(float2*)&g_P[(r0 + 8) * PCOLS + col] =
                    make_float2(acc[mt][nt][2], acc[mt][nt][3]);
        }
    }
}

// ---------------------------------------------------------------------------
// GEMM 2: h = m @ Wu2 + U1 + bu;  m = deg>0 ? A + bm + mx : 0
// ---------------------------------------------------------------------------
__global__ void __launch_bounds__(512, 1)
k_mgemm2(const float* __restrict__ bm, const float* __restrict__ bu,
         float* __restrict__ h) {
    extern __shared__ __align__(16) char sm[];
    int tid = threadIdx.x, wid = tid >> 5, lane = tid & 31;
    int wm = wid >> 2, wn = wid & 3;
    int rowbase = blockIdx.x * 128;

    // build m rows -> split -> smem A
    {
        int r = tid >> 2, kq = (tid & 3) * 32;
        int row = rowbase + r;
        char* dh = sm + SM_AH + r * SROW + kq * 2;
        char* dl = sm + SM_AL + r * SROW + kq * 2;
        int deg = (row < NN) ? g_cnt[row] : 0;
        float v[8];
#pragma unroll
        for (int c = 0; c < 32; c += 8) {
            if (row < NN && deg > 0) {
                int kg = kq + c;
                float4 a0 = *(const float4*)&g_P[row * PCOLS + kg];
                float4 a1 = *(const float4*)&g_P[row * PCOLS + kg + 4];
                float4 m0 = *(const float4*)&g_Mf[row * HID + kg];
                float4 m1 = *(const float4*)&g_Mf[row * HID + kg + 4];
                float4 b0 = *(const float4*)&bm[kg];
                float4 b1 = *(const float4*)&bm[kg + 4];
                v[0] = a0.x + b0.x + m0.x;
                v[1] = a0.y + b0.y + m0.y;
                v[2] = a0.z + b0.z + m0.z;
                v[3] = a0.w + b0.w + m0.w;
                v[4] = a1.x + b1.x + m1.x;
                v[5] = a1.y + b1.y + m1.y;
                v[6] = a1.z + b1.z + m1.z;
                v[7] = a1.w + b1.w + m1.w;
            } else {
#pragma unroll
                for (int i = 0; i < 8; ++i) v[i] = 0.f;
            }
            uint4 h4, l4;
            split8(v, h4, l4);
            *(uint4*)(dh + c * 2) = h4;
            *(uint4*)(dl + c * 2) = l4;
        }
    }
    load_B_tile(sm, 3, tid);   // Wu2
    __syncthreads();

    float acc[2][4][4];
#pragma unroll
    for (int i = 0; i < 2; ++i)
#pragma unroll
        for (int j = 0; j < 4; ++j)
#pragma unroll
            for (int q = 0; q < 4; ++q) acc[i][j][q] = 0.f;

    warp_mma_3pass(sm, acc, wm, wn, lane);

    int gid = lane >> 2, tig = lane & 3;
#pragma unroll
    for (int mt = 0; mt < 2; ++mt) {
        int r0 = rowbase + wm * 32 + mt * 16 + gid;
#pragma unroll
        for (int nt = 0; nt < 4; ++nt) {
            int col = wn * 32 + nt * 8 + tig * 2;
            float2 bb = *(const float2*)&bu[col];
            if (r0 < NN) {
                float2 uu = *(const float2*)&g_P[r0 * PCOLS + 256 + col];
                *(float2*)&h[r0 * HID + col] =
                    make_float2(acc[mt][nt][0] + uu.x + bb.x,
                                acc[mt][nt][1] + uu.y + bb.y);
            }
            if (r0 + 8 < NN) {
                float2 uu = *(const float2*)&g_P[(r0 + 8) * PCOLS + 256 + col];
                *(float2*)&h[(r0 + 8) * HID + col] =
                    make_float2(acc[mt][nt][2] + uu.x + bb.x,
                                acc[mt][nt][3] + uu.y + bb.y);
            }
        }
    }
}

// ---------------------------------------------------------------------------
extern "C" void kernel_launch(void* const* d_in, const int* in_sizes, int n_in,
                              void* d_out, int out_size) {
    const float* z   = (const float*)d_in[0];
    const float* w   = (const float*)d_in[1];
    const int*   src = (const int*)d_in[2];
    const int*   dst = (const int*)d_in[3];
    const float* Wm  = (const float*)d_in[4];
    const float* bm  = (const float*)d_in[5];
    const float* Wu  = (const float*)d_in[6];
    const float* bu  = (const float*)d_in[7];
    float* h = (float*)d_out;
    int E = in_sizes[2];

    static bool attr_done = false;
    if (!attr_done) {
        cudaFuncSetAttribute(k_mgemm1, cudaFuncAttributeMaxDynamicSharedMemorySize,
                             DYN_BYTES);
        cudaFuncSetAttribute(k_mgemm2, cudaFuncAttributeMaxDynamicSharedMemorySize,
                             DYN_BYTES);
        attr_done = true;
    }

    int nblk = (NN + 127) / 128;
    int sblk = (NN + 255) / 256;   // 196 scan chunks

    // sort edges by destination (independent of GEMM1; runs first)
    k_zero<<<sblk, 256>>>();
    k_hist<<<(E + 255) / 256, 256>>>(dst, E);
    k_scan1<<<sblk, 256>>>();
    k_scan2<<<1, 256>>>(sblk);
    k_scan3<<<sblk, 256>>>();
    k_scatter<<<(E + 255) / 256, 256>>>(src, dst, w, E);

    // weights prep + GEMM1
    k_prepw<<<(4 * 128 * 128 + 255) / 256, 256>>>(Wm, Wu);
    dim3 g1(nblk, 3);
    k_mgemm1<<<g1, 512, DYN_BYTES>>>(z);

    // per-node max (no atomics)
    k_nodemax<<<(NN * 32 + 255) / 256, 256>>>(Wm);

    // GEMM2 + epilogue
    k_mgemm2<<<nblk, 512, DYN_BYTES>>>(bm, bu, h);
}

// round 13
// speedup vs baseline: 1.9160x; 1.0397x over previous
#include <cuda_runtime.h>
#include <cuda_bf16.h>
#include <cstdint>

#define NN 50000
#define HID 128
#define PCOLS 384
#define EMAX 1048576
#define NINF __int_as_float(0xff800000)

// ---------------- scratch (device globals; no runtime allocation) ----------
__device__ float g_P[NN * PCOLS];                            // [A | B | U1] fp32
__device__ __align__(16) __nv_bfloat16 g_Bh[4 * 128 * 128];  // W blocks [n][k] hi
__device__ __align__(16) __nv_bfloat16 g_Bl[4 * 128 * 128];  // W blocks [n][k] lo
__device__ __align__(16) __nv_bfloat16 g_Mh[NN * HID];       // m rows bf16 hi
__device__ __align__(16) __nv_bfloat16 g_Ml[NN * HID];       // m rows bf16 lo
__device__ int    g_cnt[NN];       // node in-degree
__device__ int    g_off[NN];       // CSR offsets
__device__ int    g_rank[EMAX];    // within-segment rank per edge
__device__ int    g_blk[256];      // scan partials
__device__ float2 g_es[EMAX];      // packed (src bits, w) grouped by dst

// ---------------- mma/ldmatrix helpers (portable, no 'a' features) ----------
__device__ __forceinline__ uint32_t smem_u32(const void* p) {
    uint32_t a;
    asm("{ .reg .u64 t; cvta.to.shared.u64 t, %1; cvt.u32.u64 %0, t; }"
        : "=r"(a) : "l"(p));
    return a;
}
__device__ __forceinline__ void ldsm_x4(uint32_t* r, uint32_t addr) {
    asm volatile("ldmatrix.sync.aligned.m8n8.x4.shared.b16 {%0,%1,%2,%3},[%4];"
                 : "=r"(r[0]), "=r"(r[1]), "=r"(r[2]), "=r"(r[3]) : "r"(addr));
}
__device__ __forceinline__ void mma_bf16(float* c, const uint32_t* a,
                                         const uint32_t* b) {
    asm volatile(
        "mma.sync.aligned.m16n8k16.row.col.f32.bf16.bf16.f32 "
        "{%0,%1,%2,%3}, {%4,%5,%6,%7}, {%8,%9}, {%0,%1,%2,%3};"
        : "+f"(c[0]), "+f"(c[1]), "+f"(c[2]), "+f"(c[3])
        : "r"(a[0]), "r"(a[1]), "r"(a[2]), "r"(a[3]), "r"(b[0]), "r"(b[1]));
}

// split 8 fp32 -> bf16 hi/lo packed as uint4
__device__ __forceinline__ void split8(const float* v, uint4& h4, uint4& l4) {
    unsigned hs[8], ls[8];
#pragma unroll
    for (int i = 0; i < 8; ++i) {
        float a = v[i];
        __nv_bfloat16 hb = __float2bfloat16_rn(a);
        float r = a - __bfloat162float(hb);
        __nv_bfloat16 lb = __float2bfloat16_rn(r);
        hs[i] = (unsigned)*(unsigned short*)&hb;
        ls[i] = (unsigned)*(unsigned short*)&lb;
    }
    h4 = make_uint4(hs[0] | (hs[1] << 16), hs[2] | (hs[3] << 16),
                    hs[4] | (hs[5] << 16), hs[6] | (hs[7] << 16));
    l4 = make_uint4(ls[0] | (ls[1] << 16), ls[2] | (ls[3] << 16),
                    ls[4] | (ls[5] << 16), ls[6] | (ls[7] << 16));
}
// split 4 fp32 -> bf16 hi/lo packed as uint2
__device__ __forceinline__ void split4(const float* v, uint2& h2, uint2& l2) {
    unsigned hs[4], ls[4];
#pragma unroll
    for (int i = 0; i < 4; ++i) {
        float a = v[i];
        __nv_bfloat16 hb = __float2bfloat16_rn(a);
        float r = a - __bfloat162float(hb);
        __nv_bfloat16 lb = __float2bfloat16_rn(r);
        hs[i] = (unsigned)*(unsigned short*)&hb;
        ls[i] = (unsigned)*(unsigned short*)&lb;
    }
    h2 = make_uint2(hs[0] | (hs[1] << 16), hs[2] | (hs[3] << 16));
    l2 = make_uint2(ls[0] | (ls[1] << 16), ls[2] | (ls[3] << 16));
}

// SMEM tile: [128 rows][128 k] bf16, padded stride 136 (conflict-free ldmatrix)
#define SA 136
#define SROW (SA * 2)            // 272 bytes/row
#define TILE_B (128 * SROW)      // 34816
#define SM_AH 0
#define SM_AL (TILE_B)
#define SM_BH (2 * TILE_B)
#define SM_BL (3 * TILE_B)
#define DYN_BYTES (4 * TILE_B)

// ---------------------------------------------------------------------------
// prep: weight transpose+split (idx < 65536) AND zero degree counters
// ---------------------------------------------------------------------------
__global__ void k_pre(const float* __restrict__ Wm, const float* __restrict__ Wu) {
    int idx = blockIdx.x * blockDim.x + threadIdx.x;
    if (idx < 4 * 128 * 128) {
        int blk = idx >> 14, n = (idx >> 7) & 127, k = idx & 127;
        float v;
        if (blk == 0)      v = Wm[k * HID + n];
        else if (blk == 1) v = Wm[(128 + k) * HID + n];
        else if (blk == 2) v = Wu[k * HID + n];
        else               v = Wu[(128 + k) * HID + n];
        __nv_bfloat16 hb = __float2bfloat16_rn(v);
        float r = v - __bfloat162float(hb);
        g_Bh[idx] = hb;
        g_Bl[idx] = __float2bfloat16_rn(r);
    }
    int j = idx - 4 * 128 * 128;
    if (j >= 0 && j < NN) g_cnt[j] = 0;
}

// ---------------------------------------------------------------------------
// counting sort of edges by destination (rank captured during histogram)
// ---------------------------------------------------------------------------
__global__ void k_hist(const int* __restrict__ dst, int E) {
    int e = blockIdx.x * blockDim.x + threadIdx.x;
    if (e < E) g_rank[e] = atomicAdd(&g_cnt[dst[e]], 1);
}
__global__ void k_scan1() {   // per-256-chunk sums
    __shared__ int s[256];
    int t = threadIdx.x, i = blockIdx.x * 256 + t;
    s[t] = (i < NN) ? g_cnt[i] : 0;
    __syncthreads();
    for (int o = 128; o > 0; o >>= 1) {
        if (t < o) s[t] += s[t + o];
        __syncthreads();
    }
    if (t == 0) g_blk[blockIdx.x] = s[0];
}
__global__ void k_scan2(int nblk) {  // exclusive scan of partials (1 block)
    __shared__ int s[256];
    int t = threadIdx.x;
    int v = (t < nblk) ? g_blk[t] : 0;
    s[t] = v;
    __syncthreads();
    for (int o = 1; o < 256; o <<= 1) {
        int x = (t >= o) ? s[t - o] : 0;
        __syncthreads();
        s[t] += x;
        __syncthreads();
    }
    if (t < nblk) g_blk[t] = s[t] - v;
}
__global__ void k_scan3() {   // per-chunk exclusive scan + base
    __shared__ int s[256];
    int t = threadIdx.x, i = blockIdx.x * 256 + t;
    int v = (i < NN) ? g_cnt[i] : 0;
    s[t] = v;
    __syncthreads();
    for (int o = 1; o < 256; o <<= 1) {
        int x = (t >= o) ? s[t - o] : 0;
        __syncthreads();
        s[t] += x;
        __syncthreads();
    }
    if (i < NN) g_off[i] = s[t] - v + g_blk[blockIdx.x];
}
__global__ void k_scatter(const int* __restrict__ src, const int* __restrict__ dst,
                          const float* __restrict__ w, int E) {
    int e = blockIdx.x * blockDim.x + threadIdx.x;
    if (e >= E) return;
    int p = g_off[dst[e]] + g_rank[e];
    if (p < EMAX) g_es[p] = make_float2(__int_as_float(src[e]), w[e]);
}

// ---------------------------------------------------------------------------
// warp-level 32x32 mma core (3-pass error split); 16 warps in 4x4 grid
// ---------------------------------------------------------------------------
__device__ __forceinline__ void warp_mma_3pass(const char* sm, float acc[2][4][4],
                                               int wm, int wn, int lane) {
    const int pa[3] = {SM_AH, SM_AH, SM_AL};
    const int pb[3] = {SM_BH, SM_BL, SM_BH};
    uint32_t a_row  = wm * 32 + (lane & 15);
    uint32_t a_colb = (lane >> 4) * 16;
    int g = lane >> 3;
    uint32_t b_rowi = (g >> 1) * 8 + (lane & 7);
    uint32_t b_colb = (g & 1) * 16;
#pragma unroll
    for (int p = 0; p < 3; ++p) {
        uint32_t abase = smem_u32(sm + pa[p]);
        uint32_t bbase = smem_u32(sm + pb[p]);
#pragma unroll
        for (int kk = 0; kk < 8; ++kk) {
            uint32_t k0b = kk * 32;
            uint32_t a[2][4], b[4][2];
#pragma unroll
            for (int mt = 0; mt < 2; ++mt)
                ldsm_x4(a[mt], abase + (a_row + mt * 16) * SROW + k0b + a_colb);
#pragma unroll
            for (int pp = 0; pp < 2; ++pp) {
                uint32_t r[4];
                ldsm_x4(r, bbase + (wn * 32 + pp * 16 + b_rowi) * SROW + k0b + b_colb);
                b[pp * 2 + 0][0] = r[0]; b[pp * 2 + 0][1] = r[1];
                b[pp * 2 + 1][0] = r[2]; b[pp * 2 + 1][1] = r[3];
            }
#pragma unroll
            for (int mt = 0; mt < 2; ++mt)
#pragma unroll
                for (int nt = 0; nt < 4; ++nt)
                    mma_bf16(acc[mt][nt], a[mt], b[nt]);
        }
    }
}

__device__ __forceinline__ void load_B_tile(char* sm, int blk, int tid) {
    int n = tid >> 2, kq = (tid & 3) * 32;
    const uint4* bh = (const uint4*)&g_Bh[(blk * 128 + n) * 128 + kq];
    const uint4* bl = (const uint4*)&g_Bl[(blk * 128 + n) * 128 + kq];
    char* dh = sm + SM_BH + n * SROW + kq * 2;
    char* dl = sm + SM_BL + n * SROW + kq * 2;
#pragma unroll
    for (int c = 0; c < 4; ++c) {
        *(uint4*)(dh + c * 16) = bh[c];
        *(uint4*)(dl + c * 16) = bl[c];
    }
}

// ---------------------------------------------------------------------------
// GEMM 1: P = z @ [Wm1|Wm2|Wu1] — one CTA owns 128 rows, loops cb = 0..2
//   (A tile built & split ONCE per CTA)
// ---------------------------------------------------------------------------
__global__ void __launch_bounds__(512, 1)
k_mgemm1(const float* __restrict__ z) {
    extern __shared__ __align__(16) char sm[];
    int tid = threadIdx.x, wid = tid >> 5, lane = tid & 31;
    int wm = wid >> 2, wn = wid & 3;
    int rowbase = blockIdx.x * 128;

    // fill A once: split z rows (32 fp32 per thread)
    {
        int r = tid >> 2, kq = (tid & 3) * 32;
        int row = rowbase + r;
        char* dh = sm + SM_AH + r * SROW + kq * 2;
        char* dl = sm + SM_AL + r * SROW + kq * 2;
        float v[8];
#pragma unroll
        for (int c = 0; c < 32; c += 8) {
            if (row < NN) {
                *(float4*)&v[0] = *(const float4*)&z[row * HID + kq + c];
                *(float4*)&v[4] = *(const float4*)&z[row * HID + kq + c + 4];
            } else {
#pragma unroll
                for (int i = 0; i < 8; ++i) v[i] = 0.f;
            }
            uint4 h4, l4;
            split8(v, h4, l4);
            *(uint4*)(dh + c * 2) = h4;
            *(uint4*)(dl + c * 2) = l4;
        }
    }

    int gid = lane >> 2, tig = lane & 3;
    for (int cb = 0; cb < 3; ++cb) {
        load_B_tile(sm, cb, tid);
        __syncthreads();

        float acc[2][4][4];
#pragma unroll
        for (int i = 0; i < 2; ++i)
#pragma unroll
            for (int j = 0; j < 4; ++j)
#pragma unroll
                for (int q = 0; q < 4; ++q) acc[i][j][q] = 0.f;

        warp_mma_3pass(sm, acc, wm, wn, lane);

#pragma unroll
        for (int mt = 0; mt < 2; ++mt) {
            int r0 = rowbase + wm * 32 + mt * 16 + gid;
#pragma unroll
            for (int nt = 0; nt < 4; ++nt) {
                int col = cb * 128 + wn * 32 + nt * 8 + tig * 2;
                if (r0 < NN)
                    *(float2*)&g_P[r0 * PCOLS + col] =
                        make_float2(acc[mt][nt][0], acc[mt][nt][1]);
                if (r0 + 8 < NN)
                    *(float2*)&g_P[(r0 + 8) * PCOLS + col] =
                        make_float2(acc[mt][nt][2], acc[mt][nt][3]);
            }
        }
        __syncthreads();   // all warps done reading B before next overwrite
    }
}

// ---------------------------------------------------------------------------
// node max + m-row build: one warp per node, no atomics.
//   mx = max over edges (B[src] + w*r);  m = deg>0 ? A+bm+mx : 0
//   writes PRE-SPLIT bf16 hi/lo m rows for GEMM2.
// ---------------------------------------------------------------------------
__global__ void __launch_bounds__(256)
k_nodemax(const float* __restrict__ Wm, const float* __restrict__ bm) {
    int n = (blockIdx.x * blockDim.x + threadIdx.x) >> 5;
    int lane = threadIdx.x & 31;
    if (n >= NN) return;
    int deg = g_cnt[n];
    float v[4] = {0.f, 0.f, 0.f, 0.f};
    if (deg > 0) {
        float4 r4 = *(const float4*)&Wm[256 * HID + lane * 4];
        float4 mx = make_float4(NINF, NINF, NINF, NINF);
        int base = g_off[n];
        for (int c = 0; c < deg; c += 32) {
            int mcnt = min(32, deg - c);
            float2 sw = make_float2(0.f, 0.f);
            if (lane < mcnt) sw = g_es[base + c + lane];
#pragma unroll 4
            for (int j = 0; j < mcnt; ++j) {
                int   s  = __shfl_sync(0xffffffffu, __float_as_int(sw.x), j);
                float we = __shfl_sync(0xffffffffu, sw.y, j);
                float4 b = *(const float4*)&g_P[s * PCOLS + 128 + lane * 4];
                mx.x = fmaxf(mx.x, fmaf(we, r4.x, b.x));
                mx.y = fmaxf(mx.y, fmaf(we, r4.y, b.y));
                mx.z = fmaxf(mx.z, fmaf(we, r4.z, b.z));
                mx.w = fmaxf(mx.w, fmaf(we, r4.w, b.w));
            }
        }
        float4 a  = *(const float4*)&g_P[n * PCOLS + lane * 4];
        float4 bb = *(const float4*)&bm[lane * 4];
        v[0] = a.x + bb.x + mx.x;
        v[1] = a.y + bb.y + mx.y;
        v[2] = a.z + bb.z + mx.z;
        v[3] = a.w + bb.w + mx.w;
    }
    uint2 h2, l2;
    split4(v, h2, l2);
    *(uint2*)&g_Mh[n * HID + lane * 4] = h2;
    *(uint2*)&g_Ml[n * HID + lane * 4] = l2;
}

// ---------------------------------------------------------------------------
// GEMM 2: h = m @ Wu2 + U1 + bu   (A-fill is a pure copy of pre-split m)
// ---------------------------------------------------------------------------
__global__ void __launch_bounds__(512, 1)
k_mgemm2(const float* __restrict__ bu, float* __restrict__ h) {
    extern __shared__ __align__(16) char sm[];
    int tid = threadIdx.x, wid = tid >> 5, lane = tid & 31;
    int wm = wid >> 2, wn = wid & 3;
    int rowbase = blockIdx.x * 128;

    // A-fill: copy pre-split m rows (32 bf16 per tile half per thread)
    {
        int r = tid >> 2, kq = (tid & 3) * 32;
        int row = rowbase + r;
        char* dh = sm + SM_AH + r * SROW + kq * 2;
        char* dl = sm + SM_AL + r * SROW + kq * 2;
        if (row < NN) {
            const uint4* mh = (const uint4*)&g_Mh[row * HID + kq];
            const uint4* ml = (const uint4*)&g_Ml[row * HID + kq];
#pragma unroll
            for (int c = 0; c < 4; ++c) {
                *(uint4*)(dh + c * 16) = mh[c];
                *(uint4*)(dl + c * 16) = ml[c];
            }
        } else {
            uint4 zz = make_uint4(0, 0, 0, 0);
#pragma unroll
            for (int c = 0; c < 4; ++c) {
                *(uint4*)(dh + c * 16) = zz;
                *(uint4*)(dl + c * 16) = zz;
            }
        }
    }
    load_B_tile(sm, 3, tid);   // Wu2
    __syncthreads();

    float acc[2][4][4];
#pragma unroll
    for (int i = 0; i < 2; ++i)
#pragma unroll
        for (int j = 0; j < 4; ++j)
#pragma unroll
            for (int q = 0; q < 4; ++q) acc[i][j][q] = 0.f;

    warp_mma_3pass(sm, acc, wm, wn, lane);

    int gid = lane >> 2, tig = lane & 3;
#pragma unroll
    for (int mt = 0; mt < 2; ++mt) {
        int r0 = rowbase + wm * 32 + mt * 16 + gid;
#pragma unroll
        for (int nt = 0; nt < 4; ++nt) {
            int col = wn * 32 + nt * 8 + tig * 2;
            float2 bb = *(const float2*)&bu[col];
            if (r0 < NN) {
                float2 uu = *(const float2*)&g_P[r0 * PCOLS + 256 + col];
                *(float2*)&h[r0 * HID + col] =
                    make_float2(acc[mt][nt][0] + uu.x + bb.x,
                                acc[mt][nt][1] + uu.y + bb.y);
            }
            if (r0 + 8 < NN) {
                float2 uu = *(const float2*)&g_P[(r0 + 8) * PCOLS + 256 + col];
                *(float2*)&h[(r0 + 8) * HID + col] =
                    make_float2(acc[mt][nt][2] + uu.x + bb.x,
                                acc[mt][nt][3] + uu.y + bb.y);
            }
        }
    }
}

// ---------------------------------------------------------------------------
extern "C" void kernel_launch(void* const* d_in, const int* in_sizes, int n_in,
                              void* d_out, int out_size) {
    const float* z   = (const float*)d_in[0];
    const float* w   = (const float*)d_in[1];
    const int*   src = (const int*)d_in[2];
    const int*   dst = (const int*)d_in[3];
    const float* Wm  = (const float*)d_in[4];
    const float* bm  = (const float*)d_in[5];
    const float* Wu  = (const float*)d_in[6];
    const float* bu  = (const float*)d_in[7];
    float* h = (float*)d_out;
    int E = in_sizes[2];

    static bool attr_done = false;
    if (!attr_done) {
        cudaFuncSetAttribute(k_mgemm1, cudaFuncAttributeMaxDynamicSharedMemorySize,
                             DYN_BYTES);
        cudaFuncSetAttribute(k_mgemm2, cudaFuncAttributeMaxDynamicSharedMemorySize,
                             DYN_BYTES);
        attr_done = true;
    }

    int nblk = (NN + 127) / 128;
    int sblk = (NN + 255) / 256;

    // weights prep + counter zero (one kernel)
    k_pre<<<(4 * 128 * 128 + NN + 255) / 256, 256>>>(Wm, Wu);

    // counting sort by destination (rank captured in histogram pass)
    k_hist<<<(E + 255) / 256, 256>>>(dst, E);
    k_scan1<<<sblk, 256>>>();
    k_scan2<<<1, 256>>>(sblk);
    k_scan3<<<sblk, 256>>>();
    k_scatter<<<(E + 255) / 256, 256>>>(src, dst, w, E);

    // GEMM1 (A built once per CTA, loops over 3 weight blocks)
    k_mgemm1<<<nblk, 512, DYN_BYTES>>>(z);

    // per-node max + m-row build (pre-split bf16)
    k_nodemax<<<(NN * 32 + 255) / 256, 256>>>(Wm, bm);

    // GEMM2 + epilogue
    k_mgemm2<<<nblk, 512, DYN_BYTES>>>(bu, h);
}

// round 17
// speedup vs baseline: 2.0424x; 1.0660x over previous
#include <cuda_runtime.h>
#include <cuda_bf16.h>
#include <cstdint>

#define NN 50000
#define HID 128
#define PCOLS 384
#define EMAX 1048576
#define NINF __int_as_float(0xff800000)

// ---------------- scratch (device globals; no runtime allocation) ----------
__device__ float g_P[NN * PCOLS];                            // [A | B | U1] fp32
__device__ __align__(16) __nv_bfloat16 g_Bh[4 * 128 * 128];  // W blocks [n][k] hi
__device__ __align__(16) __nv_bfloat16 g_Bl[4 * 128 * 128];  // W blocks [n][k] lo
__device__ __align__(16) __nv_bfloat16 g_Mh[NN * HID];       // m rows bf16 hi
__device__ __align__(16) __nv_bfloat16 g_Ml[NN * HID];       // m rows bf16 lo
__device__ int    g_cnt[NN];       // node in-degree
__device__ int    g_off[NN];       // CSR offsets
__device__ int    g_rank[EMAX];    // within-segment rank per edge
__device__ float2 g_es[EMAX];      // packed (src bits, w) grouped by dst

// ---------------- mma/ldmatrix helpers (portable, no 'a' features) ----------
__device__ __forceinline__ uint32_t smem_u32(const void* p) {
    uint32_t a;
    asm("{ .reg .u64 t; cvta.to.shared.u64 t, %1; cvt.u32.u64 %0, t; }"
        : "=r"(a) : "l"(p));
    return a;
}
__device__ __forceinline__ void ldsm_x4(uint32_t* r, uint32_t addr) {
    asm volatile("ldmatrix.sync.aligned.m8n8.x4.shared.b16 {%0,%1,%2,%3},[%4];"
                 : "=r"(r[0]), "=r"(r[1]), "=r"(r[2]), "=r"(r[3]) : "r"(addr));
}
__device__ __forceinline__ void mma_bf16(float* c, const uint32_t* a,
                                         const uint32_t* b) {
    asm volatile(
        "mma.sync.aligned.m16n8k16.row.col.f32.bf16.bf16.f32 "
        "{%0,%1,%2,%3}, {%4,%5,%6,%7}, {%8,%9}, {%0,%1,%2,%3};"
        : "+f"(c[0]), "+f"(c[1]), "+f"(c[2]), "+f"(c[3])
        : "r"(a[0]), "r"(a[1]), "r"(a[2]), "r"(a[3]), "r"(b[0]), "r"(b[1]));
}

// split fp32 -> bf16 hi/lo
__device__ __forceinline__ void split8(const float* v, uint4& h4, uint4& l4) {
    unsigned hs[8], ls[8];
#pragma unroll
    for (int i = 0; i < 8; ++i) {
        float a = v[i];
        __nv_bfloat16 hb = __float2bfloat16_rn(a);
        float r = a - __bfloat162float(hb);
        __nv_bfloat16 lb = __float2bfloat16_rn(r);
        hs[i] = (unsigned)*(unsigned short*)&hb;
        ls[i] = (unsigned)*(unsigned short*)&lb;
    }
    h4 = make_uint4(hs[0] | (hs[1] << 16), hs[2] | (hs[3] << 16),
                    hs[4] | (hs[5] << 16), hs[6] | (hs[7] << 16));
    l4 = make_uint4(ls[0] | (ls[1] << 16), ls[2] | (ls[3] << 16),
                    ls[4] | (ls[5] << 16), ls[6] | (ls[7] << 16));
}
__device__ __forceinline__ void split4(const float* v, uint2& h2, uint2& l2) {
    unsigned hs[4], ls[4];
#pragma unroll
    for (int i = 0; i < 4; ++i) {
        float a = v[i];
        __nv_bfloat16 hb = __float2bfloat16_rn(a);
        float r = a - __bfloat162float(hb);
        __nv_bfloat16 lb = __float2bfloat16_rn(r);
        hs[i] = (unsigned)*(unsigned short*)&hb;
        ls[i] = (unsigned)*(unsigned short*)&lb;
    }
    h2 = make_uint2(hs[0] | (hs[1] << 16), hs[2] | (hs[3] << 16));
    l2 = make_uint2(ls[0] | (ls[1] << 16), ls[2] | (ls[3] << 16));
}

// SMEM tile: [128 rows][128 k] bf16, padded stride 136 (conflict-free ldmatrix)
#define SA 136
#define SROW (SA * 2)
#define TILE_B (128 * SROW)
#define SM_AH 0
#define SM_AL (TILE_B)
#define SM_BH (2 * TILE_B)
#define SM_BL (3 * TILE_B)
#define DYN_BYTES (4 * TILE_B)

// ---------------------------------------------------------------------------
// prep kernels
// ---------------------------------------------------------------------------
__global__ void k_prepw(const float* __restrict__ Wm, const float* __restrict__ Wu) {
    int idx = blockIdx.x * blockDim.x + threadIdx.x;
    if (idx >= 4 * 128 * 128) return;
    int blk = idx >> 14, n = (idx >> 7) & 127, k = idx & 127;
    float v;
    if (blk == 0)      v = Wm[k * HID + n];
    else if (blk == 1) v = Wm[(128 + k) * HID + n];
    else if (blk == 2) v = Wu[k * HID + n];
    else               v = Wu[(128 + k) * HID + n];
    __nv_bfloat16 hb = __float2bfloat16_rn(v);
    float r = v - __bfloat162float(hb);
    g_Bh[idx] = hb;
    g_Bl[idx] = __float2bfloat16_rn(r);
}
__global__ void k_zero() {
    int i = blockIdx.x * blockDim.x + threadIdx.x;
    if (i < NN) g_cnt[i] = 0;
}

// ---------------------------------------------------------------------------
// counting sort by destination
// ---------------------------------------------------------------------------
__global__ void k_hist(const int* __restrict__ dst, int E) {
    int e = blockIdx.x * blockDim.x + threadIdx.x;
    if (e < E) g_rank[e] = atomicAdd(&g_cnt[dst[e]], 1);
}
// single-block exclusive scan of g_cnt -> g_off (1024 threads)
__global__ void __launch_bounds__(1024)
k_scanall() {
    __shared__ int s[1024];
    int t = threadIdx.x;
    const int C = (NN + 1023) / 1024;
    int b0 = t * C, b1 = min(b0 + C, NN);
    int sum = 0;
    for (int i = b0; i < b1; ++i) sum += g_cnt[i];
    s[t] = sum;
    __syncthreads();
    int v = sum;
    for (int o = 1; o < 1024; o <<= 1) {
        int x = (t >= o) ? s[t - o] : 0;
        __syncthreads();
        s[t] += x;
        __syncthreads();
    }
    int run = s[t] - v;
    for (int i = b0; i < b1; ++i) {
        int c = g_cnt[i];
        g_off[i] = run;
        run += c;
    }
}
__global__ void k_scatter(const int* __restrict__ src, const int* __restrict__ dst,
                          const float* __restrict__ w, int E) {
    int e = blockIdx.x * blockDim.x + threadIdx.x;
    if (e >= E) return;
    int p = g_off[dst[e]] + g_rank[e];
    if (p < EMAX) g_es[p] = make_float2(__int_as_float(src[e]), w[e]);
}

// ---------------------------------------------------------------------------
// warp-level 32x32 mma core (3-pass error split); 16 warps in 4x4 grid
// ---------------------------------------------------------------------------
__device__ __forceinline__ void warp_mma_3pass(const char* sm, float acc[2][4][4],
                                               int wm, int wn, int lane) {
    const int pa[3] = {SM_AH, SM_AH, SM_AL};
    const int pb[3] = {SM_BH, SM_BL, SM_BH};
    uint32_t a_row  = wm * 32 + (lane & 15);
    uint32_t a_colb = (lane >> 4) * 16;
    int g = lane >> 3;
    uint32_t b_rowi = (g >> 1) * 8 + (lane & 7);
    uint32_t b_colb = (g & 1) * 16;
#pragma unroll
    for (int p = 0; p < 3; ++p) {
        uint32_t abase = smem_u32(sm + pa[p]);
        uint32_t bbase = smem_u32(sm + pb[p]);
#pragma unroll
        for (int kk = 0; kk < 8; ++kk) {
            uint32_t k0b = kk * 32;
            uint32_t a[2][4], b[4][2];
#pragma unroll
            for (int mt = 0; mt < 2; ++mt)
                ldsm_x4(a[mt], abase + (a_row + mt * 16) * SROW + k0b + a_colb);
#pragma unroll
            for (int pp = 0; pp < 2; ++pp) {
                uint32_t r[4];
                ldsm_x4(r, bbase + (wn * 32 + pp * 16 + b_rowi) * SROW + k0b + b_colb);
                b[pp * 2 + 0][0] = r[0]; b[pp * 2 + 0][1] = r[1];
                b[pp * 2 + 1][0] = r[2]; b[pp * 2 + 1][1] = r[3];
            }
#pragma unroll
            for (int mt = 0; mt < 2; ++mt)
#pragma unroll
                for (int nt = 0; nt < 4; ++nt)
                    mma_bf16(acc[mt][nt], a[mt], b[nt]);
        }
    }
}

__device__ __forceinline__ void load_B_tile(char* sm, int blk, int tid) {
    int n = tid >> 2, kq = (tid & 3) * 32;
    const uint4* bh = (const uint4*)&g_Bh[(blk * 128 + n) * 128 + kq];
    const uint4* bl = (const uint4*)&g_Bl[(blk * 128 + n) * 128 + kq];
    char* dh = sm + SM_BH + n * SROW + kq * 2;
    char* dl = sm + SM_BL + n * SROW + kq * 2;
#pragma unroll
    for (int c = 0; c < 4; ++c) {
        *(uint4*)(dh + c * 16) = bh[c];
        *(uint4*)(dl + c * 16) = bl[c];
    }
}

// A-fill from z: split 32 fp32 per thread into smem hi/lo tiles
__device__ __forceinline__ void fill_A_z(char* sm, const float* __restrict__ z,
                                         int rowbase, int tid) {
    int r = tid >> 2, kq = (tid & 3) * 32;
    int row = rowbase + r;
    char* dh = sm + SM_AH + r * SROW + kq * 2;
    char* dl = sm + SM_AL + r * SROW + kq * 2;
    float v[8];
#pragma unroll
    for (int c = 0; c < 32; c += 8) {
        if (row < NN) {
            *(float4*)&v[0] = *(const float4*)&z[row * HID + kq + c];
            *(float4*)&v[4] = *(const float4*)&z[row * HID + kq + c + 4];
        } else {
#pragma unroll
            for (int i = 0; i < 8; ++i) v[i] = 0.f;
        }
        uint4 h4, l4;
        split8(v, h4, l4);
        *(uint4*)(dh + c * 2) = h4;
        *(uint4*)(dl + c * 2) = l4;
    }
}

__device__ __forceinline__ void store_acc(float acc[2][4][4], int rowbase,
                                          int colbase, int wm, int wn, int lane) {
    int gid = lane >> 2, tig = lane & 3;
#pragma unroll
    for (int mt = 0; mt < 2; ++mt) {
        int r0 = rowbase + wm * 32 + mt * 16 + gid;
#pragma unroll
        for (int nt = 0; nt < 4; ++nt) {
            int col = colbase + wn * 32 + nt * 8 + tig * 2;
            if (r0 < NN)
                *(float2*)&g_P[r0 * PCOLS + col] =
                    make_float2(acc[mt][nt][0], acc[mt][nt][1]);
            if (r0 + 8 < NN)
                *(float2*)&g_P[(r0 + 8) * PCOLS + col] =
                    make_float2(acc[mt][nt][2], acc[mt][nt][3]);
        }
    }
}

// ---------------------------------------------------------------------------
// GEMM B: P[:,128:256] = z @ Wm2  (the only block nodemax needs)
// ---------------------------------------------------------------------------
__global__ void __launch_bounds__(512, 1)
k_gemmB(const float* __restrict__ z) {
    extern __shared__ __align__(16) char sm[];
    int tid = threadIdx.x, wid = tid >> 5, lane = tid & 31;
    int wm = wid >> 2, wn = wid & 3;
    int rowbase = blockIdx.x * 128;

    fill_A_z(sm, z, rowbase, tid);
    load_B_tile(sm, 1, tid);
    __syncthreads();

    float acc[2][4][4];
#pragma unroll
    for (int i = 0; i < 2; ++i)
#pragma unroll
        for (int j = 0; j < 4; ++j)
#pragma unroll
            for (int q = 0; q < 4; ++q) acc[i][j][q] = 0.f;
    warp_mma_3pass(sm, acc, wm, wn, lane);
    store_acc(acc, rowbase, 128, wm, wn, lane);
}

// ---------------------------------------------------------------------------
// GEMM AU: P[:,0:128] = z@Wm1, P[:,256:384] = z@Wu1 (overlaps nodemax)
// ---------------------------------------------------------------------------
__global__ void __launch_bounds__(512, 1)
k_gemmAU(const float* __restrict__ z) {
    extern __shared__ __align__(16) char sm[];
    int tid = threadIdx.x, wid = tid >> 5, lane = tid & 31;
    int wm = wid >> 2, wn = wid & 3;
    int rowbase = blockIdx.x * 128;

    fill_A_z(sm, z, rowbase, tid);

    for (int ci = 0; ci < 2; ++ci) {
        int cb = ci * 2;                 // weight blocks 0 (Wm1) and 2 (Wu1)
        load_B_tile(sm, cb, tid);
        __syncthreads();

        float acc[2][4][4];
#pragma unroll
        for (int i = 0; i < 2; ++i)
#pragma unroll
            for (int j = 0; j < 4; ++j)
#pragma unroll
                for (int q = 0; q < 4; ++q) acc[i][j][q] = 0.f;
        warp_mma_3pass(sm, acc, wm, wn, lane);
        store_acc(acc, rowbase, cb * 128, wm, wn, lane);
        __syncthreads();
    }
}

// ---------------------------------------------------------------------------
// node max + m-row build: one warp per node, no atomics.
// ---------------------------------------------------------------------------
__global__ void __launch_bounds__(256)
k_nodemax(const float* __restrict__ Wm, const float* __restrict__ bm) {
    int n = (blockIdx.x * blockDim.x + threadIdx.x) >> 5;
    int lane = threadIdx.x & 31;
    if (n >= NN) return;
    int deg = g_cnt[n];
    float v[4] = {0.f, 0.f, 0.f, 0.f};
    if (deg > 0) {
        float4 r4 = *(const float4*)&Wm[256 * HID + lane * 4];
        float4 mx = make_float4(NINF, NINF, NINF, NINF);
        int base = g_off[n];
        for (int c = 0; c < deg; c += 32) {
            int mcnt = min(32, deg - c);
            float2 sw = make_float2(0.f, 0.f);
            if (lane < mcnt) sw = g_es[base + c + lane];
#pragma unroll 4
            for (int j = 0; j < mcnt; ++j) {
                int   s  = __shfl_sync(0xffffffffu, __float_as_int(sw.x), j);
                float we = __shfl_sync(0xffffffffu, sw.y, j);
                float4 b = *(const float4*)&g_P[s * PCOLS + 128 + lane * 4];
                mx.x = fmaxf(mx.x, fmaf(we, r4.x, b.x));
                mx.y = fmaxf(mx.y, fmaf(we, r4.y, b.y));
                mx.z = fmaxf(mx.z, fmaf(we, r4.z, b.z));
                mx.w = fmaxf(mx.w, fmaf(we, r4.w, b.w));
            }
        }
        float4 a  = *(const float4*)&g_P[n * PCOLS + lane * 4];
        float4 bb = *(const float4*)&bm[lane * 4];
        v[0] = a.x + bb.x + mx.x;
        v[1] = a.y + bb.y + mx.y;
        v[2] = a.z + bb.z + mx.z;
        v[3] = a.w + bb.w + mx.w;
    }
    uint2 h2, l2;
    split4(v, h2, l2);
    *(uint2*)&g_Mh[n * HID + lane * 4] = h2;
    *(uint2*)&g_Ml[n * HID + lane * 4] = l2;
}

// ---------------------------------------------------------------------------
// GEMM 2: h = m @ Wu2 + U1 + bu   (A-fill is a pure copy of pre-split m)
// ---------------------------------------------------------------------------
__global__ void __launch_bounds__(512, 1)
k_mgemm2(const float* __restrict__ bu, float* __restrict__ h) {
    extern __shared__ __align__(16) char sm[];
    int tid = threadIdx.x, wid = tid >> 5, lane = tid & 31;
    int wm = wid >> 2, wn = wid & 3;
    int rowbase = blockIdx.x * 128;

    {
        int r = tid >> 2, kq = (tid & 3) * 32;
        int row = rowbase + r;
        char* dh = sm + SM_AH + r * SROW + kq * 2;
        char* dl = sm + SM_AL + r * SROW + kq * 2;
        if (row < NN) {
            const uint4* mh = (const uint4*)&g_Mh[row * HID + kq];
            const uint4* ml = (const uint4*)&g_Ml[row * HID + kq];
#pragma unroll
            for (int c = 0; c < 4; ++c) {
                *(uint4*)(dh + c * 16) = mh[c];
                *(uint4*)(dl + c * 16) = ml[c];
            }
        } else {
            uint4 zz = make_uint4(0, 0, 0, 0);
#pragma unroll
            for (int c = 0; c < 4; ++c) {
                *(uint4*)(dh + c * 16) = zz;
                *(uint4*)(dl + c * 16) = zz;
            }
        }
    }
    load_B_tile(sm, 3, tid);   // Wu2
    __syncthreads();

    float acc[2][4][4];
#pragma unroll
    for (int i = 0; i < 2; ++i)
#pragma unroll
        for (int j = 0; j < 4; ++j)
#pragma unroll
            for (int q = 0; q < 4; ++q) acc[i][j][q] = 0.f;

    warp_mma_3pass(sm, acc, wm, wn, lane);

    int gid = lane >> 2, tig = lane & 3;
#pragma unroll
    for (int mt = 0; mt < 2; ++mt) {
        int r0 = rowbase + wm * 32 + mt * 16 + gid;
#pragma unroll
        for (int nt = 0; nt < 4; ++nt) {
            int col = wn * 32 + nt * 8 + tig * 2;
            float2 bb = *(const float2*)&bu[col];
            if (r0 < NN) {
                float2 uu = *(const float2*)&g_P[r0 * PCOLS + 256 + col];
                *(float2*)&h[r0 * HID + col] =
                    make_float2(acc[mt][nt][0] + uu.x + bb.x,
                                acc[mt][nt][1] + uu.y + bb.y);
            }
            if (r0 + 8 < NN) {
                float2 uu = *(const float2*)&g_P[(r0 + 8) * PCOLS + 256 + col];
                *(float2*)&h[(r0 + 8) * HID + col] =
                    make_float2(acc[mt][nt][2] + uu.x + bb.x,
                                acc[mt][nt][3] + uu.y + bb.y);
            }
        }
    }
}

// ---------------------------------------------------------------------------
extern "C" void kernel_launch(void* const* d_in, const int* in_sizes, int n_in,
                              void* d_out, int out_size) {
    const float* z   = (const float*)d_in[0];
    const float* w   = (const float*)d_in[1];
    const int*   src = (const int*)d_in[2];
    const int*   dst = (const int*)d_in[3];
    const float* Wm  = (const float*)d_in[4];
    const float* bm  = (const float*)d_in[5];
    const float* Wu  = (const float*)d_in[6];
    const float* bu  = (const float*)d_in[7];
    float* h = (float*)d_out;
    int E = in_sizes[2];

    static cudaStream_t s1 = nullptr, s2 = nullptr;
    static cudaEvent_t eStart, eSort, eB, eAU;
    if (!s1) {
        cudaStreamCreateWithFlags(&s1, cudaStreamNonBlocking);
        cudaStreamCreateWithFlags(&s2, cudaStreamNonBlocking);
        cudaEventCreateWithFlags(&eStart, cudaEventDisableTiming);
        cudaEventCreateWithFlags(&eSort, cudaEventDisableTiming);
        cudaEventCreateWithFlags(&eB, cudaEventDisableTiming);
        cudaEventCreateWithFlags(&eAU, cudaEventDisableTiming);
        cudaFuncSetAttribute(k_gemmB, cudaFuncAttributeMaxDynamicSharedMemorySize,
                             DYN_BYTES);
        cudaFuncSetAttribute(k_gemmAU, cudaFuncAttributeMaxDynamicSharedMemorySize,
                             DYN_BYTES);
        cudaFuncSetAttribute(k_mgemm2, cudaFuncAttributeMaxDynamicSharedMemorySize,
                             DYN_BYTES);
    }

    int nblk = (NN + 127) / 128;

    // fork: sort chain on s1 (independent of GEMMs)
    cudaEventRecord(eStart, 0);
    cudaStreamWaitEvent(s1, eStart, 0);
    k_zero<<<(NN + 255) / 256, 256, 0, s1>>>();
    k_hist<<<(E + 255) / 256, 256, 0, s1>>>(dst, E);
    k_scanall<<<1, 1024, 0, s1>>>();
    k_scatter<<<(E + 255) / 256, 256, 0, s1>>>(src, dst, w, E);
    cudaEventRecord(eSort, s1);

    // main stream: weights -> B-block GEMM (nodemax's only GEMM dependency)
    k_prepw<<<(4 * 128 * 128 + 255) / 256, 256>>>(Wm, Wu);
    k_gemmB<<<nblk, 512, DYN_BYTES>>>(z);
    cudaEventRecord(eB, 0);

    // s2: A+U1 GEMM, overlapped with nodemax
    cudaStreamWaitEvent(s2, eB, 0);
    k_gemmAU<<<nblk, 512, DYN_BYTES, s2>>>(z);
    cudaEventRecord(eAU, s2);

    // main: nodemax after sort + gemmB; gemm2 after nodemax + gemmAU
    cudaStreamWaitEvent(0, eSort, 0);
    k_nodemax<<<(NN * 32 + 255) / 256, 256>>>(Wm, bm);
    cudaStreamWaitEvent(0, eAU, 0);
    k_mgemm2<<<nblk, 512, DYN_BYTES>>>(bu, h);
}